// round 8
// baseline (speedup 1.0000x reference)
#include <cuda_runtime.h>
#include <cuda_bf16.h>
#include <math.h>
#include <stdint.h>

// Problem constants
#define HH 16
#define DHH 64
static constexpr int Bc   = 2;
static constexpr int Nq   = 1024;
static constexpr int NCTX = 2048;
static constexpr int DIM  = 1024;
static constexpr int NMEM = 16;
static constexpr int JJ   = NCTX + NMEM;   // 2064

// ---------------- scratch (device globals) ----------------------------------
static constexpr size_t QN_ELEMS   = (size_t)Bc * HH * Nq * DHH;
static constexpr size_t KN_ELEMS   = (size_t)Bc * HH * JJ * DHH;
static constexpr size_t DOTS_ELEMS = (size_t)Bc * HH * Nq * (size_t)JJ;
static constexpr size_t CAT_ELEMS  = (size_t)Bc * Nq * HH * DHH;

__device__ float g_qn[QN_ELEMS];
__device__ float g_kn[KN_ELEMS];
__device__ float g_vv[KN_ELEMS];
__device__ float g_dots[DOTS_ELEMS];
__device__ float g_cat[CAT_ELEMS];
__device__ float g_scale[HH];

// ---------------- tiny helper kernels ---------------------------------------

__global__ void scale_kernel(float* __restrict__ out, const float* __restrict__ p) {
    int h = threadIdx.x;
    if (h < HH) out[h] = 1.0f / fmaxf(expf(p[h]), 0.01f);
}

__global__ void memfill_kernel(float* __restrict__ kn, float* __restrict__ vv,
                               const float* __restrict__ mk, const float* __restrict__ mv) {
    int idx = blockIdx.x * blockDim.x + threadIdx.x;
    const int total = HH * NMEM * DHH;
    if (idx >= total) return;
    int h   = idx / (NMEM * DHH);
    int rem = idx % (NMEM * DHH);
    int m = rem / DHH, d = rem % DHH;
    float k = mk[idx], v = mv[idx];
    for (int b = 0; b < Bc; b++) {
        size_t o = (((size_t)(b * HH + h) * JJ) + m) * DHH + d;
        kn[o] = k; vv[o] = v;
    }
}

__global__ void l2norm_kernel(float* __restrict__ buf, int rows) {
    int row = blockIdx.x * 8 + (threadIdx.x >> 5);
    if (row >= rows) return;
    int lane = threadIdx.x & 31;
    float2* p = reinterpret_cast<float2*>(buf + (size_t)row * DHH);
    float2 v = p[lane];
    float ss = v.x * v.x + v.y * v.y;
    #pragma unroll
    for (int o = 16; o; o >>= 1) ss += __shfl_xor_sync(0xffffffffu, ss, o);
    float inv = 1.0f / fmaxf(sqrtf(ss), 1e-12f);
    v.x *= inv; v.y *= inv;
    p[lane] = v;
}

// ---------------- fused talking-heads pre-mix + softmax + post-mix ----------
// blockDim = 384 (12 warps); __launch_bounds__ keeps regfile feasible.
__global__ void __launch_bounds__(384)
mix_softmax_kernel(float* __restrict__ dots,
                   const float* __restrict__ th_pre,
                   const float* __restrict__ th_post) {
    extern __shared__ float sh[];                 // [16][JJ]
    __shared__ float s_pre[HH * HH], s_post[HH * HH];
    __shared__ float red[HH][12];
    __shared__ float gmax[HH], gsum[HH], Mmat[HH * HH];

    const int bi = blockIdx.x;
    const int b = bi / Nq, i = bi % Nq;
    const int tid = threadIdx.x;                  // 0..383
    const int warp = tid >> 5, lane = tid & 31;

    if (tid < 256) { s_pre[tid] = th_pre[tid]; s_post[tid] = th_post[tid]; }

    for (int h = 0; h < HH; h++) {
        const float* src = dots + (((size_t)(b * HH + h) * Nq + i) * JJ);
        for (int j = tid; j < JJ; j += 384) sh[h * JJ + j] = src[j];
    }
    __syncthreads();

    float lmax[HH];
    #pragma unroll
    for (int g = 0; g < HH; g++) lmax[g] = -1e30f;
    for (int j = tid; j < JJ; j += 384) {
        float d[HH];
        #pragma unroll
        for (int h = 0; h < HH; h++) d[h] = sh[h * JJ + j];
        #pragma unroll
        for (int g = 0; g < HH; g++) {
            float m = 0.0f;
            #pragma unroll
            for (int h = 0; h < HH; h++) m = fmaf(s_pre[g * HH + h], d[h], m);
            sh[g * JJ + j] = m;
            lmax[g] = fmaxf(lmax[g], m);
        }
    }
    __syncthreads();
    #pragma unroll
    for (int g = 0; g < HH; g++) {
        float v = lmax[g];
        #pragma unroll
        for (int o = 16; o; o >>= 1) v = fmaxf(v, __shfl_xor_sync(0xffffffffu, v, o));
        if (lane == 0) red[g][warp] = v;
    }
    __syncthreads();
    if (tid < HH) {
        float v = red[tid][0];
        #pragma unroll
        for (int w = 1; w < 12; w++) v = fmaxf(v, red[tid][w]);
        gmax[tid] = v;
    }
    __syncthreads();

    float lsum[HH];
    #pragma unroll
    for (int g = 0; g < HH; g++) lsum[g] = 0.0f;
    for (int j = tid; j < JJ; j += 384) {
        #pragma unroll
        for (int g = 0; g < HH; g++) {
            float e = __expf(sh[g * JJ + j] - gmax[g]);
            sh[g * JJ + j] = e;
            lsum[g] += e;
        }
    }
    __syncthreads();
    #pragma unroll
    for (int g = 0; g < HH; g++) {
        float v = lsum[g];
        #pragma unroll
        for (int o = 16; o; o >>= 1) v += __shfl_xor_sync(0xffffffffu, v, o);
        if (lane == 0) red[g][warp] = v;
    }
    __syncthreads();
    if (tid < HH) {
        float v = 0.0f;
        #pragma unroll
        for (int w = 0; w < 12; w++) v += red[tid][w];
        gsum[tid] = v;
    }
    __syncthreads();
    if (tid < 256) Mmat[tid] = s_post[tid] / gsum[tid & 15];
    __syncthreads();

    for (int j = tid; j < JJ; j += 384) {
        float e[HH];
        #pragma unroll
        for (int h = 0; h < HH; h++) e[h] = sh[h * JJ + j];
        #pragma unroll
        for (int g = 0; g < HH; g++) {
            float o = 0.0f;
            #pragma unroll
            for (int h = 0; h < HH; h++) o = fmaf(Mmat[g * HH + h], e[h], o);
            dots[(((size_t)(b * HH + g) * Nq + i) * JJ) + j] = o;
        }
    }
}

// ---------------- bf16x2 (3-term split) tensor-core GEMM --------------------
// x = hi + lo with hi = bf16(x), lo = bf16(x - hi).
// a*b ~= a_lo*b_hi + a_hi*b_lo + a_hi*b_hi  via mma.m16n8k16.bf16 (fp32 accum)

__device__ __forceinline__ uint32_t pack_bf2(__nv_bfloat16 a, __nv_bfloat16 b) {
    return ((uint32_t)__bfloat16_as_ushort(b) << 16) | (uint32_t)__bfloat16_as_ushort(a);
}
__device__ __forceinline__ void split_bf16(float x, __nv_bfloat16& h, __nv_bfloat16& l) {
    h = __float2bfloat16(x);
    l = __float2bfloat16(x - __bfloat162float(h));
}

__device__ __forceinline__ void mma_bf16(float* c, const uint32_t* a, const uint32_t* b) {
    asm volatile(
        "mma.sync.aligned.m16n8k16.row.col.f32.bf16.bf16.f32 "
        "{%0,%1,%2,%3}, {%4,%5,%6,%7}, {%8,%9}, {%0,%1,%2,%3};"
        : "+f"(c[0]), "+f"(c[1]), "+f"(c[2]), "+f"(c[3])
        : "r"(a[0]), "r"(a[1]), "r"(a[2]), "r"(a[3]),
          "r"(b[0]), "r"(b[1]));
}

template<int BM, int BN, int BK, int WM, int WN, bool TRANSB>
__global__ void __launch_bounds__((BM / WM) * (BN / WN) * 32)
bf16x2gemm_kernel(
    int M, int Nc, int K,
    const float* __restrict__ A, int lda, long sA,
    const float* __restrict__ B, int ldb, long sB,
    float* __restrict__ Cout, long sC,
    const float* __restrict__ alphaVec,
    float beta, int mode, int p1, int p2, int p3)
{
    constexpr int NWARP = (BM / WM) * (BN / WN);
    constexpr int NTH   = NWARP * 32;
    constexpr int KP    = BK / 2;        // k-pairs per row
    constexpr int PA    = KP + 4;        // A pitch in u32 words
    constexpr int PB    = KP + 3;        // B pitch in u32 words
    constexpr int MFR = WM / 16;
    constexpr int NFR = WN / 8;

    __shared__ uint32_t AsH[BM * PA];
    __shared__ uint32_t AsL[BM * PA];
    __shared__ uint32_t BsH[BN * PB];    // n-major, k-pair-minor
    __shared__ uint32_t BsL[BN * PB];

    const int z = blockIdx.z;
    const float* Ab = A + (long)z * sA;
    const float* Bb = B + (long)z * sB;

    const int tid  = threadIdx.x;
    const int warp = tid >> 5;
    const int lane = tid & 31;
    const int g    = lane >> 2;
    const int tg   = lane & 3;
    const int wr   = warp / (BN / WN);
    const int wc   = warp % (BN / WN);
    const int rowBase = blockIdx.y * BM;
    const int colBase = blockIdx.x * BN;

    float acc[MFR][NFR][4];
    #pragma unroll
    for (int i = 0; i < MFR; i++)
        #pragma unroll
        for (int j = 0; j < NFR; j++)
            #pragma unroll
            for (int q = 0; q < 4; q++) acc[i][j][q] = 0.0f;

    for (int k0 = 0; k0 < K; k0 += BK) {
        // ---- A tile: row-major M x K, float4 along k -> 2 packed u32
        #pragma unroll
        for (int idx = tid; idx < BM * (BK / 4); idx += NTH) {
            int r  = idx / (BK / 4);
            int k4 = (idx % (BK / 4)) * 4;
            int gr = rowBase + r;
            float4 v = make_float4(0.f, 0.f, 0.f, 0.f);
            if (gr < M && (k0 + k4) < K)
                v = *reinterpret_cast<const float4*>(&Ab[(long)gr * lda + k0 + k4]);
            __nv_bfloat16 h0, l0, h1, l1, h2, l2, h3, l3;
            split_bf16(v.x, h0, l0); split_bf16(v.y, h1, l1);
            split_bf16(v.z, h2, l2); split_bf16(v.w, h3, l3);
            int w = r * PA + k4 / 2;
            AsH[w]     = pack_bf2(h0, h1); AsH[w + 1] = pack_bf2(h2, h3);
            AsL[w]     = pack_bf2(l0, l1); AsL[w + 1] = pack_bf2(l2, l3);
        }
        // ---- B tile -> n-major packed pairs
        if (!TRANSB) {
            __nv_bfloat16* bh = reinterpret_cast<__nv_bfloat16*>(BsH);
            __nv_bfloat16* bl = reinterpret_cast<__nv_bfloat16*>(BsL);
            #pragma unroll
            for (int idx = tid; idx < BK * BN; idx += NTH) {
                int r = idx / BN;         // k within tile
                int c = idx % BN;         // n within tile
                int gc = colBase + c;
                float v = 0.0f;
                if ((k0 + r) < K && gc < Nc)
                    v = Bb[(long)(k0 + r) * ldb + gc];
                __nv_bfloat16 h, l;
                split_bf16(v, h, l);
                bh[c * (2 * PB) + r] = h;
                bl[c * (2 * PB) + r] = l;
            }
        } else {
            #pragma unroll
            for (int idx = tid; idx < BN * (BK / 4); idx += NTH) {
                int c  = idx / (BK / 4);
                int k4 = (idx % (BK / 4)) * 4;
                int gc = colBase + c;
                float4 v = make_float4(0.f, 0.f, 0.f, 0.f);
                if (gc < Nc && (k0 + k4) < K)
                    v = *reinterpret_cast<const float4*>(&Bb[(long)gc * ldb + k0 + k4]);
                __nv_bfloat16 h0, l0, h1, l1, h2, l2, h3, l3;
                split_bf16(v.x, h0, l0); split_bf16(v.y, h1, l1);
                split_bf16(v.z, h2, l2); split_bf16(v.w, h3, l3);
                int w = c * PB + k4 / 2;
                BsH[w]     = pack_bf2(h0, h1); BsH[w + 1] = pack_bf2(h2, h3);
                BsL[w]     = pack_bf2(l0, l1); BsL[w + 1] = pack_bf2(l2, l3);
            }
        }
        __syncthreads();

        #pragma unroll
        for (int kk = 0; kk < BK; kk += 16) {
            const int kp = kk / 2;       // base pair index (0 or 8)
            uint32_t afH[MFR][4], afL[MFR][4];
            uint32_t bfH[NFR][2], bfL[NFR][2];
            #pragma unroll
            for (int mi = 0; mi < MFR; mi++) {
                int mrow = wr * WM + mi * 16 + g;
                int i00 = (mrow    ) * PA + kp + tg;
                int i10 = (mrow + 8) * PA + kp + tg;
                afH[mi][0] = AsH[i00];     afL[mi][0] = AsL[i00];
                afH[mi][1] = AsH[i10];     afL[mi][1] = AsL[i10];
                afH[mi][2] = AsH[i00 + 4]; afL[mi][2] = AsL[i00 + 4];
                afH[mi][3] = AsH[i10 + 4]; afL[mi][3] = AsL[i10 + 4];
            }
            #pragma unroll
            for (int ni = 0; ni < NFR; ni++) {
                int ncol = wc * WN + ni * 8 + g;
                int j0 = ncol * PB + kp + tg;
                bfH[ni][0] = BsH[j0];     bfL[ni][0] = BsL[j0];
                bfH[ni][1] = BsH[j0 + 4]; bfL[ni][1] = BsL[j0 + 4];
            }
            #pragma unroll
            for (int mi = 0; mi < MFR; mi++)
                #pragma unroll
                for (int ni = 0; ni < NFR; ni++) {
                    float* c = acc[mi][ni];
                    mma_bf16(c, afL[mi], bfH[ni]);   // lo*hi
                    mma_bf16(c, afH[mi], bfL[ni]);   // hi*lo
                    mma_bf16(c, afH[mi], bfH[ni]);   // hi*hi
                }
        }
        __syncthreads();
    }

    float alpha = 1.0f;
    if (alphaVec) alpha = alphaVec[z % HH];

    #pragma unroll
    for (int mi = 0; mi < MFR; mi++) {
        #pragma unroll
        for (int half = 0; half < 2; half++) {
            int gr = rowBase + wr * WM + mi * 16 + g + half * 8;
            if (gr >= M) continue;
            #pragma unroll
            for (int ni = 0; ni < NFR; ni++) {
                #pragma unroll
                for (int e = 0; e < 2; e++) {
                    int gc = colBase + wc * WN + ni * 8 + tg * 2 + e;
                    if (gc >= Nc) continue;
                    float val = alpha * acc[mi][ni][half * 2 + e];
                    if (mode == 0) {
                        float* cp = Cout + (long)gr * p1 + gc;
                        *cp = (beta == 0.0f) ? val : fmaf(beta, *cp, val);
                    } else if (mode == 1) {
                        int b = gr / p1;
                        int rr = gr - b * p1;
                        int h = gc >> 6, d = gc & 63;
                        Cout[(((long)(b * HH + h) * p2 + p3 + rr) << 6) + d] = val;
                    } else if (mode == 2) {
                        int b = z >> 4, h = z & 15;
                        Cout[(((long)(b * p1 + gr) * HH + h) << 6) + gc] = val;
                    } else {
                        Cout[(long)z * sC + (long)gr * p1 + gc] = val;
                    }
                }
            }
        }
    }
}

// ---------------- host launch ------------------------------------------------

static constexpr size_t MIX_SMEM = (size_t)HH * JJ * sizeof(float); // 132096

extern "C" void kernel_launch(void* const* d_in, const int* in_sizes, int n_in,
                              void* d_out, int out_size)
{
    (void)in_sizes; (void)n_in; (void)out_size;
    const float* x   = (const float*)d_in[0];
    const float* ctx = (const float*)d_in[1];
    const float* wq[2]     = {(const float*)d_in[2],  (const float*)d_in[5]};
    const float* wk[2]     = {(const float*)d_in[3],  (const float*)d_in[6]};
    const float* wv[2]     = {(const float*)d_in[4],  (const float*)d_in[7]};
    const float* thpre[2]  = {(const float*)d_in[8],  (const float*)d_in[10]};
    const float* thpost[2] = {(const float*)d_in[9],  (const float*)d_in[11]};
    const float* scp[2]    = {(const float*)d_in[12], (const float*)d_in[13]};
    const float* mk[2]     = {(const float*)d_in[14], (const float*)d_in[16]};
    const float* mv[2]     = {(const float*)d_in[15], (const float*)d_in[17]};
    const float* hs[2]     = {(const float*)d_in[18], (const float*)d_in[19]};
    const float* wo[2]     = {(const float*)d_in[20], (const float*)d_in[21]};
    float* out = (float*)d_out;

    float *qn, *kn, *vv, *dots, *cat, *scl;
    cudaGetSymbolAddress((void**)&qn,   g_qn);
    cudaGetSymbolAddress((void**)&kn,   g_kn);
    cudaGetSymbolAddress((void**)&vv,   g_vv);
    cudaGetSymbolAddress((void**)&dots, g_dots);
    cudaGetSymbolAddress((void**)&cat,  g_cat);
    cudaGetSymbolAddress((void**)&scl,  g_scale);

    cudaFuncSetAttribute(mix_softmax_kernel,
                         cudaFuncAttributeMaxDynamicSharedMemorySize, (int)MIX_SMEM);

    for (int l = 0; l < 2; l++) {
        scale_kernel<<<1, 16>>>(scl, scp[l]);

        // Q = x @ wq  -> qn [b][h][n][d]
        bf16x2gemm_kernel<128, 128, 32, 64, 32, false><<<dim3(8, 16, 1), 256>>>(
            Bc * Nq, DIM, DIM, x, DIM, 0, wq[l], DIM, 0, qn, 0,
            nullptr, 0.0f, 1, Nq, Nq, 0);

        const float* c = ctx + (size_t)l * Bc * NCTX * DIM;
        // K = ctx @ wk -> kn rows [NMEM..J)
        bf16x2gemm_kernel<128, 128, 32, 64, 32, false><<<dim3(8, 32, 1), 256>>>(
            Bc * NCTX, DIM, DIM, c, DIM, 0, wk[l], DIM, 0, kn, 0,
            nullptr, 0.0f, 1, NCTX, JJ, NMEM);
        // V = ctx @ wv -> vv rows [NMEM..J)
        bf16x2gemm_kernel<128, 128, 32, 64, 32, false><<<dim3(8, 32, 1), 256>>>(
            Bc * NCTX, DIM, DIM, c, DIM, 0, wv[l], DIM, 0, vv, 0,
            nullptr, 0.0f, 1, NCTX, JJ, NMEM);

        memfill_kernel<<<64, 256>>>(kn, vv, mk[l], mv[l]);

        l2norm_kernel<<<(Bc * HH * Nq + 7) / 8, 256>>>(qn, Bc * HH * Nq);
        l2norm_kernel<<<(Bc * HH * JJ + 7) / 8, 256>>>(kn, Bc * HH * JJ);

        // dots = scale[h] * qn @ kn^T   (batched over z = b*16+h)
        bf16x2gemm_kernel<128, 128, 32, 64, 32, true><<<dim3(17, 8, 32), 256>>>(
            Nq, JJ, DHH, qn, DHH, (long)Nq * DHH, kn, DHH, (long)JJ * DHH,
            dots, (long)Nq * JJ, scl, 0.0f, 3, JJ, 0, 0);

        // talking-heads pre-mix + softmax + post-mix (in place)
        mix_softmax_kernel<<<Bc * Nq, 384, MIX_SMEM>>>(dots, thpre[l], thpost[l]);

        // out_heads = hs[h] * attn @ v -> cat [b][n][h][d]
        bf16x2gemm_kernel<128, 64, 32, 64, 32, false><<<dim3(1, 8, 32), 128>>>(
            Nq, DHH, JJ, dots, JJ, (long)Nq * JJ, vv, DHH, (long)JJ * DHH,
            cat, 0, hs[l], 0.0f, 2, Nq, 0, 0);

        // out (+)= cat @ wo
        bf16x2gemm_kernel<128, 128, 32, 64, 32, false><<<dim3(8, 16, 1), 256>>>(
            Bc * Nq, DIM, DIM, cat, DIM, 0, wo[l], DIM, 0, out, 0,
            nullptr, (l == 0 ? 0.0f : 1.0f), 0, DIM, 0, 0);
    }
}

// round 9
// speedup vs baseline: 1.4550x; 1.4550x over previous
#include <cuda_runtime.h>
#include <cuda_bf16.h>
#include <math.h>
#include <stdint.h>

// Problem constants
#define HH 16
#define DHH 64
static constexpr int Bc   = 2;
static constexpr int Nq   = 1024;
static constexpr int NCTX = 2048;
static constexpr int DIM  = 1024;
static constexpr int NMEM = 16;
static constexpr int JJ   = NCTX + NMEM;   // 2064

// ---------------- scratch (device globals) ----------------------------------
static constexpr size_t QN_ELEMS   = (size_t)Bc * HH * Nq * DHH;
static constexpr size_t KN_ELEMS   = (size_t)Bc * HH * JJ * DHH;
static constexpr size_t DOTS_ELEMS = (size_t)Bc * HH * Nq * (size_t)JJ;
static constexpr size_t CAT_ELEMS  = (size_t)Bc * Nq * HH * DHH;

__device__ float g_qn[QN_ELEMS];
__device__ float g_kn[KN_ELEMS];
__device__ float g_vv[KN_ELEMS];
__device__ float g_dots[DOTS_ELEMS];
__device__ float g_cat[CAT_ELEMS];
__device__ float g_scale[HH];

// ---------------- tiny helper kernels ---------------------------------------

__global__ void scale_kernel(float* __restrict__ out, const float* __restrict__ p) {
    int h = threadIdx.x;
    if (h < HH) out[h] = 1.0f / fmaxf(expf(p[h]), 0.01f);
}

__global__ void memfill_kernel(float* __restrict__ kn, float* __restrict__ vv,
                               const float* __restrict__ mk, const float* __restrict__ mv) {
    int idx = blockIdx.x * blockDim.x + threadIdx.x;
    const int total = HH * NMEM * DHH;
    if (idx >= total) return;
    int h   = idx / (NMEM * DHH);
    int rem = idx % (NMEM * DHH);
    int m = rem / DHH, d = rem % DHH;
    float k = mk[idx], v = mv[idx];
    for (int b = 0; b < Bc; b++) {
        size_t o = (((size_t)(b * HH + h) * JJ) + m) * DHH + d;
        kn[o] = k; vv[o] = v;
    }
}

__global__ void l2norm_kernel(float* __restrict__ buf, int rows) {
    int row = blockIdx.x * 8 + (threadIdx.x >> 5);
    if (row >= rows) return;
    int lane = threadIdx.x & 31;
    float2* p = reinterpret_cast<float2*>(buf + (size_t)row * DHH);
    float2 v = p[lane];
    float ss = v.x * v.x + v.y * v.y;
    #pragma unroll
    for (int o = 16; o; o >>= 1) ss += __shfl_xor_sync(0xffffffffu, ss, o);
    float inv = 1.0f / fmaxf(sqrtf(ss), 1e-12f);
    v.x *= inv; v.y *= inv;
    p[lane] = v;
}

// ---------------- fused talking-heads pre-mix + softmax + post-mix ----------
// 256 threads, NO launch bounds (proven R5 config: no register spills).
__global__ void mix_softmax_kernel(float* __restrict__ dots,
                                   const float* __restrict__ th_pre,
                                   const float* __restrict__ th_post) {
    extern __shared__ float sh[];                 // [16][JJ]
    __shared__ float s_pre[HH * HH], s_post[HH * HH];
    __shared__ float red[HH][8];
    __shared__ float gmax[HH], gsum[HH], Mmat[HH * HH];

    const int bi = blockIdx.x;
    const int b = bi / Nq, i = bi % Nq;
    const int tid = threadIdx.x;                  // blockDim = 256
    const int warp = tid >> 5, lane = tid & 31;

    s_pre[tid]  = th_pre[tid];
    s_post[tid] = th_post[tid];

    for (int h = 0; h < HH; h++) {
        const float* src = dots + (((size_t)(b * HH + h) * Nq + i) * JJ);
        for (int j = tid; j < JJ; j += 256) sh[h * JJ + j] = src[j];
    }
    __syncthreads();

    float lmax[HH];
    #pragma unroll
    for (int g = 0; g < HH; g++) lmax[g] = -1e30f;
    for (int j = tid; j < JJ; j += 256) {
        float d[HH];
        #pragma unroll
        for (int h = 0; h < HH; h++) d[h] = sh[h * JJ + j];
        #pragma unroll
        for (int g = 0; g < HH; g++) {
            float m = 0.0f;
            #pragma unroll
            for (int h = 0; h < HH; h++) m = fmaf(s_pre[g * HH + h], d[h], m);
            sh[g * JJ + j] = m;
            lmax[g] = fmaxf(lmax[g], m);
        }
    }
    __syncthreads();
    #pragma unroll
    for (int g = 0; g < HH; g++) {
        float v = lmax[g];
        #pragma unroll
        for (int o = 16; o; o >>= 1) v = fmaxf(v, __shfl_xor_sync(0xffffffffu, v, o));
        if (lane == 0) red[g][warp] = v;
    }
    __syncthreads();
    if (tid < HH) {
        float v = red[tid][0];
        #pragma unroll
        for (int w = 1; w < 8; w++) v = fmaxf(v, red[tid][w]);
        gmax[tid] = v;
    }
    __syncthreads();

    float lsum[HH];
    #pragma unroll
    for (int g = 0; g < HH; g++) lsum[g] = 0.0f;
    for (int j = tid; j < JJ; j += 256) {
        #pragma unroll
        for (int g = 0; g < HH; g++) {
            float e = __expf(sh[g * JJ + j] - gmax[g]);
            sh[g * JJ + j] = e;
            lsum[g] += e;
        }
    }
    __syncthreads();
    #pragma unroll
    for (int g = 0; g < HH; g++) {
        float v = lsum[g];
        #pragma unroll
        for (int o = 16; o; o >>= 1) v += __shfl_xor_sync(0xffffffffu, v, o);
        if (lane == 0) red[g][warp] = v;
    }
    __syncthreads();
    if (tid < HH) {
        float v = 0.0f;
        #pragma unroll
        for (int w = 0; w < 8; w++) v += red[tid][w];
        gsum[tid] = v;
    }
    __syncthreads();
    Mmat[tid] = s_post[tid] / gsum[tid & 15];
    __syncthreads();

    for (int j = tid; j < JJ; j += 256) {
        float e[HH];
        #pragma unroll
        for (int h = 0; h < HH; h++) e[h] = sh[h * JJ + j];
        #pragma unroll
        for (int g = 0; g < HH; g++) {
            float o = 0.0f;
            #pragma unroll
            for (int h = 0; h < HH; h++) o = fmaf(Mmat[g * HH + h], e[h], o);
            dots[(((size_t)(b * HH + g) * Nq + i) * JJ) + j] = o;
        }
    }
}

// ---------------- bf16x2 (3-term split) tensor-core GEMM --------------------
// x = hi + lo with hi = bf16(x), lo = bf16(x - hi).
// a*b ~= a_lo*b_hi + a_hi*b_lo + a_hi*b_hi  via mma.m16n8k16.bf16 (fp32 accum)

__device__ __forceinline__ uint32_t pack_bf2(__nv_bfloat16 a, __nv_bfloat16 b) {
    return ((uint32_t)__bfloat16_as_ushort(b) << 16) | (uint32_t)__bfloat16_as_ushort(a);
}
__device__ __forceinline__ void split_bf16(float x, __nv_bfloat16& h, __nv_bfloat16& l) {
    h = __float2bfloat16(x);
    l = __float2bfloat16(x - __bfloat162float(h));
}

__device__ __forceinline__ void mma_bf16(float* c, const uint32_t* a, const uint32_t* b) {
    asm volatile(
        "mma.sync.aligned.m16n8k16.row.col.f32.bf16.bf16.f32 "
        "{%0,%1,%2,%3}, {%4,%5,%6,%7}, {%8,%9}, {%0,%1,%2,%3};"
        : "+f"(c[0]), "+f"(c[1]), "+f"(c[2]), "+f"(c[3])
        : "r"(a[0]), "r"(a[1]), "r"(a[2]), "r"(a[3]),
          "r"(b[0]), "r"(b[1]));
}

template<int BM, int BN, int BK, int WM, int WN, bool TRANSB>
__global__ void __launch_bounds__((BM / WM) * (BN / WN) * 32)
bf16x2gemm_kernel(
    int M, int Nc, int K,
    const float* __restrict__ A, int lda, long sA,
    const float* __restrict__ B, int ldb, long sB,
    float* __restrict__ Cout, long sC,
    const float* __restrict__ alphaVec,
    float beta, int mode, int p1, int p2, int p3)
{
    constexpr int NWARP = (BM / WM) * (BN / WN);
    constexpr int NTH   = NWARP * 32;
    constexpr int KP    = BK / 2;        // k-pairs per row
    constexpr int PA    = KP + 4;        // A pitch in u32 words
    constexpr int PB    = KP + 3;        // B pitch in u32 words
    constexpr int MFR = WM / 16;
    constexpr int NFR = WN / 8;

    __shared__ uint32_t AsH[BM * PA];
    __shared__ uint32_t AsL[BM * PA];
    __shared__ uint32_t BsH[BN * PB];    // n-major, k-pair-minor
    __shared__ uint32_t BsL[BN * PB];

    const int z = blockIdx.z;
    const float* Ab = A + (long)z * sA;
    const float* Bb = B + (long)z * sB;

    const int tid  = threadIdx.x;
    const int warp = tid >> 5;
    const int lane = tid & 31;
    const int g    = lane >> 2;
    const int tg   = lane & 3;
    const int wr   = warp / (BN / WN);
    const int wc   = warp % (BN / WN);
    const int rowBase = blockIdx.y * BM;
    const int colBase = blockIdx.x * BN;

    float acc[MFR][NFR][4];
    #pragma unroll
    for (int i = 0; i < MFR; i++)
        #pragma unroll
        for (int j = 0; j < NFR; j++)
            #pragma unroll
            for (int q = 0; q < 4; q++) acc[i][j][q] = 0.0f;

    for (int k0 = 0; k0 < K; k0 += BK) {
        // ---- A tile: row-major M x K, float4 along k -> 2 packed u32
        #pragma unroll
        for (int idx = tid; idx < BM * (BK / 4); idx += NTH) {
            int r  = idx / (BK / 4);
            int k4 = (idx % (BK / 4)) * 4;
            int gr = rowBase + r;
            float4 v = make_float4(0.f, 0.f, 0.f, 0.f);
            if (gr < M && (k0 + k4) < K)
                v = *reinterpret_cast<const float4*>(&Ab[(long)gr * lda + k0 + k4]);
            __nv_bfloat16 h0, l0, h1, l1, h2, l2, h3, l3;
            split_bf16(v.x, h0, l0); split_bf16(v.y, h1, l1);
            split_bf16(v.z, h2, l2); split_bf16(v.w, h3, l3);
            int w = r * PA + k4 / 2;
            AsH[w]     = pack_bf2(h0, h1); AsH[w + 1] = pack_bf2(h2, h3);
            AsL[w]     = pack_bf2(l0, l1); AsL[w + 1] = pack_bf2(l2, l3);
        }
        // ---- B tile -> n-major packed pairs
        if (!TRANSB) {
            __nv_bfloat16* bh = reinterpret_cast<__nv_bfloat16*>(BsH);
            __nv_bfloat16* bl = reinterpret_cast<__nv_bfloat16*>(BsL);
            #pragma unroll
            for (int idx = tid; idx < BK * BN; idx += NTH) {
                int r = idx / BN;         // k within tile
                int c = idx % BN;         // n within tile
                int gc = colBase + c;
                float v = 0.0f;
                if ((k0 + r) < K && gc < Nc)
                    v = Bb[(long)(k0 + r) * ldb + gc];
                __nv_bfloat16 h, l;
                split_bf16(v, h, l);
                bh[c * (2 * PB) + r] = h;
                bl[c * (2 * PB) + r] = l;
            }
        } else {
            #pragma unroll
            for (int idx = tid; idx < BN * (BK / 4); idx += NTH) {
                int c  = idx / (BK / 4);
                int k4 = (idx % (BK / 4)) * 4;
                int gc = colBase + c;
                float4 v = make_float4(0.f, 0.f, 0.f, 0.f);
                if (gc < Nc && (k0 + k4) < K)
                    v = *reinterpret_cast<const float4*>(&Bb[(long)gc * ldb + k0 + k4]);
                __nv_bfloat16 h0, l0, h1, l1, h2, l2, h3, l3;
                split_bf16(v.x, h0, l0); split_bf16(v.y, h1, l1);
                split_bf16(v.z, h2, l2); split_bf16(v.w, h3, l3);
                int w = c * PB + k4 / 2;
                BsH[w]     = pack_bf2(h0, h1); BsH[w + 1] = pack_bf2(h2, h3);
                BsL[w]     = pack_bf2(l0, l1); BsL[w + 1] = pack_bf2(l2, l3);
            }
        }
        __syncthreads();

        #pragma unroll
        for (int kk = 0; kk < BK; kk += 16) {
            const int kp = kk / 2;       // base pair index (0 or 8)
            uint32_t afH[MFR][4], afL[MFR][4];
            uint32_t bfH[NFR][2], bfL[NFR][2];
            #pragma unroll
            for (int mi = 0; mi < MFR; mi++) {
                int mrow = wr * WM + mi * 16 + g;
                int i00 = (mrow    ) * PA + kp + tg;
                int i10 = (mrow + 8) * PA + kp + tg;
                afH[mi][0] = AsH[i00];     afL[mi][0] = AsL[i00];
                afH[mi][1] = AsH[i10];     afL[mi][1] = AsL[i10];
                afH[mi][2] = AsH[i00 + 4]; afL[mi][2] = AsL[i00 + 4];
                afH[mi][3] = AsH[i10 + 4]; afL[mi][3] = AsL[i10 + 4];
            }
            #pragma unroll
            for (int ni = 0; ni < NFR; ni++) {
                int ncol = wc * WN + ni * 8 + g;
                int j0 = ncol * PB + kp + tg;
                bfH[ni][0] = BsH[j0];     bfL[ni][0] = BsL[j0];
                bfH[ni][1] = BsH[j0 + 4]; bfL[ni][1] = BsL[j0 + 4];
            }
            #pragma unroll
            for (int mi = 0; mi < MFR; mi++)
                #pragma unroll
                for (int ni = 0; ni < NFR; ni++) {
                    float* c = acc[mi][ni];
                    mma_bf16(c, afL[mi], bfH[ni]);   // lo*hi
                    mma_bf16(c, afH[mi], bfL[ni]);   // hi*lo
                    mma_bf16(c, afH[mi], bfH[ni]);   // hi*hi
                }
        }
        __syncthreads();
    }

    float alpha = 1.0f;
    if (alphaVec) alpha = alphaVec[z % HH];

    #pragma unroll
    for (int mi = 0; mi < MFR; mi++) {
        #pragma unroll
        for (int half = 0; half < 2; half++) {
            int gr = rowBase + wr * WM + mi * 16 + g + half * 8;
            if (gr >= M) continue;
            #pragma unroll
            for (int ni = 0; ni < NFR; ni++) {
                #pragma unroll
                for (int e = 0; e < 2; e++) {
                    int gc = colBase + wc * WN + ni * 8 + tg * 2 + e;
                    if (gc >= Nc) continue;
                    float val = alpha * acc[mi][ni][half * 2 + e];
                    if (mode == 0) {
                        float* cp = Cout + (long)gr * p1 + gc;
                        *cp = (beta == 0.0f) ? val : fmaf(beta, *cp, val);
                    } else if (mode == 1) {
                        int b = gr / p1;
                        int rr = gr - b * p1;
                        int h = gc >> 6, d = gc & 63;
                        Cout[(((long)(b * HH + h) * p2 + p3 + rr) << 6) + d] = val;
                    } else if (mode == 2) {
                        int b = z >> 4, h = z & 15;
                        Cout[(((long)(b * p1 + gr) * HH + h) << 6) + gc] = val;
                    } else {
                        Cout[(long)z * sC + (long)gr * p1 + gc] = val;
                    }
                }
            }
        }
    }
}

// ---------------- host launch ------------------------------------------------

static constexpr size_t MIX_SMEM = (size_t)HH * JJ * sizeof(float); // 132096

extern "C" void kernel_launch(void* const* d_in, const int* in_sizes, int n_in,
                              void* d_out, int out_size)
{
    (void)in_sizes; (void)n_in; (void)out_size;
    const float* x   = (const float*)d_in[0];
    const float* ctx = (const float*)d_in[1];
    const float* wq[2]     = {(const float*)d_in[2],  (const float*)d_in[5]};
    const float* wk[2]     = {(const float*)d_in[3],  (const float*)d_in[6]};
    const float* wv[2]     = {(const float*)d_in[4],  (const float*)d_in[7]};
    const float* thpre[2]  = {(const float*)d_in[8],  (const float*)d_in[10]};
    const float* thpost[2] = {(const float*)d_in[9],  (const float*)d_in[11]};
    const float* scp[2]    = {(const float*)d_in[12], (const float*)d_in[13]};
    const float* mk[2]     = {(const float*)d_in[14], (const float*)d_in[16]};
    const float* mv[2]     = {(const float*)d_in[15], (const float*)d_in[17]};
    const float* hs[2]     = {(const float*)d_in[18], (const float*)d_in[19]};
    const float* wo[2]     = {(const float*)d_in[20], (const float*)d_in[21]};
    float* out = (float*)d_out;

    float *qn, *kn, *vv, *dots, *cat, *scl;
    cudaGetSymbolAddress((void**)&qn,   g_qn);
    cudaGetSymbolAddress((void**)&kn,   g_kn);
    cudaGetSymbolAddress((void**)&vv,   g_vv);
    cudaGetSymbolAddress((void**)&dots, g_dots);
    cudaGetSymbolAddress((void**)&cat,  g_cat);
    cudaGetSymbolAddress((void**)&scl,  g_scale);

    cudaFuncSetAttribute(mix_softmax_kernel,
                         cudaFuncAttributeMaxDynamicSharedMemorySize, (int)MIX_SMEM);

    for (int l = 0; l < 2; l++) {
        scale_kernel<<<1, 16>>>(scl, scp[l]);

        // Q = x @ wq  -> qn [b][h][n][d]
        bf16x2gemm_kernel<128, 128, 32, 64, 32, false><<<dim3(8, 16, 1), 256>>>(
            Bc * Nq, DIM, DIM, x, DIM, 0, wq[l], DIM, 0, qn, 0,
            nullptr, 0.0f, 1, Nq, Nq, 0);

        const float* c = ctx + (size_t)l * Bc * NCTX * DIM;
        // K = ctx @ wk -> kn rows [NMEM..J)
        bf16x2gemm_kernel<128, 128, 32, 64, 32, false><<<dim3(8, 32, 1), 256>>>(
            Bc * NCTX, DIM, DIM, c, DIM, 0, wk[l], DIM, 0, kn, 0,
            nullptr, 0.0f, 1, NCTX, JJ, NMEM);
        // V = ctx @ wv -> vv rows [NMEM..J)
        bf16x2gemm_kernel<128, 128, 32, 64, 32, false><<<dim3(8, 32, 1), 256>>>(
            Bc * NCTX, DIM, DIM, c, DIM, 0, wv[l], DIM, 0, vv, 0,
            nullptr, 0.0f, 1, NCTX, JJ, NMEM);

        memfill_kernel<<<64, 256>>>(kn, vv, mk[l], mv[l]);

        l2norm_kernel<<<(Bc * HH * Nq + 7) / 8, 256>>>(qn, Bc * HH * Nq);
        l2norm_kernel<<<(Bc * HH * JJ + 7) / 8, 256>>>(kn, Bc * HH * JJ);

        // dots = scale[h] * qn @ kn^T   (batched over z = b*16+h)
        bf16x2gemm_kernel<128, 128, 32, 64, 32, true><<<dim3(17, 8, 32), 256>>>(
            Nq, JJ, DHH, qn, DHH, (long)Nq * DHH, kn, DHH, (long)JJ * DHH,
            dots, (long)Nq * JJ, scl, 0.0f, 3, JJ, 0, 0);

        // talking-heads pre-mix + softmax + post-mix (in place)
        mix_softmax_kernel<<<Bc * Nq, 256, MIX_SMEM>>>(dots, thpre[l], thpost[l]);

        // out_heads = hs[h] * attn @ v -> cat [b][n][h][d]
        bf16x2gemm_kernel<128, 64, 32, 64, 32, false><<<dim3(1, 8, 32), 128>>>(
            Nq, DHH, JJ, dots, JJ, (long)Nq * JJ, vv, DHH, (long)JJ * DHH,
            cat, 0, hs[l], 0.0f, 2, Nq, 0, 0);

        // out (+)= cat @ wo
        bf16x2gemm_kernel<128, 128, 32, 64, 32, false><<<dim3(8, 16, 1), 256>>>(
            Bc * Nq, DIM, DIM, cat, DIM, 0, wo[l], DIM, 0, out, 0,
            nullptr, (l == 0 ? 0.0f : 1.0f), 0, DIM, 0, 0);
    }
}

// round 12
// speedup vs baseline: 1.5920x; 1.0941x over previous
#include <cuda_runtime.h>
#include <cuda_bf16.h>
#include <math.h>
#include <stdint.h>

// Problem constants
#define HH 16
#define DHH 64
static constexpr int Bc   = 2;
static constexpr int Nq   = 1024;
static constexpr int NCTX = 2048;
static constexpr int DIM  = 1024;
static constexpr int NMEM = 16;
static constexpr int JJ   = NCTX + NMEM;   // 2064
static constexpr int JJP  = 2080;          // padded to multiple of 32 (BK)
static constexpr int HDH  = HH * DHH;      // 1024

// ---------------- scratch (device globals) ----------------------------------
__device__ float g_qn[(size_t)Bc * HH * Nq * DHH];
__device__ float g_kn[(size_t)Bc * HH * JJ * DHH];
__device__ float g_dots[(size_t)Bc * HH * Nq * (size_t)JJ];
__device__ float g_scale[HH];

// pre-split bf16 operand arrays (hi / lo)
__device__ __align__(16) __nv_bfloat16 g_xH [(size_t)Bc * Nq * DIM];
__device__ __align__(16) __nv_bfloat16 g_xL [(size_t)Bc * Nq * DIM];
__device__ __align__(16) __nv_bfloat16 g_cH [(size_t)Bc * NCTX * DIM];
__device__ __align__(16) __nv_bfloat16 g_cL [(size_t)Bc * NCTX * DIM];
__device__ __align__(16) __nv_bfloat16 g_wTH[(size_t)HDH * DIM];
__device__ __align__(16) __nv_bfloat16 g_wTL[(size_t)HDH * DIM];
__device__ __align__(16) __nv_bfloat16 g_qnH[(size_t)Bc * HH * Nq * DHH];
__device__ __align__(16) __nv_bfloat16 g_qnL[(size_t)Bc * HH * Nq * DHH];
__device__ __align__(16) __nv_bfloat16 g_knH[(size_t)Bc * HH * JJ * DHH];
__device__ __align__(16) __nv_bfloat16 g_knL[(size_t)Bc * HH * JJ * DHH];
__device__ __align__(16) __nv_bfloat16 g_vTH[(size_t)Bc * HH * DHH * JJP];
__device__ __align__(16) __nv_bfloat16 g_vTL[(size_t)Bc * HH * DHH * JJP];
__device__ __align__(16) __nv_bfloat16 g_atH[(size_t)Bc * HH * Nq * JJP];
__device__ __align__(16) __nv_bfloat16 g_atL[(size_t)Bc * HH * Nq * JJP];
__device__ __align__(16) __nv_bfloat16 g_ctH[(size_t)Bc * Nq * HDH];
__device__ __align__(16) __nv_bfloat16 g_ctL[(size_t)Bc * Nq * HDH];

// ---------------- split helpers ---------------------------------------------
__device__ __forceinline__ uint32_t pack_bf2(__nv_bfloat16 a, __nv_bfloat16 b) {
    return ((uint32_t)__bfloat16_as_ushort(b) << 16) | (uint32_t)__bfloat16_as_ushort(a);
}
__device__ __forceinline__ void split_bf16(float x, __nv_bfloat16& h, __nv_bfloat16& l) {
    h = __float2bfloat16(x);
    l = __float2bfloat16(x - __bfloat162float(h));
}

// ---------------- tiny kernels ----------------------------------------------

__global__ void scale_kernel(float* __restrict__ out, const float* __restrict__ p) {
    int h = threadIdx.x;
    if (h < HH) out[h] = 1.0f / fmaxf(expf(p[h]), 0.01f);
}

// elementwise fp32 -> bf16 hi/lo split (float4 granularity)
__global__ void split_kernel(__nv_bfloat16* __restrict__ H, __nv_bfloat16* __restrict__ L,
                             const float* __restrict__ src, long n4) {
    long i = blockIdx.x * (long)blockDim.x + threadIdx.x;
    if (i >= n4) return;
    float4 v = reinterpret_cast<const float4*>(src)[i];
    __nv_bfloat16 h0,l0,h1,l1,h2,l2,h3,l3;
    split_bf16(v.x,h0,l0); split_bf16(v.y,h1,l1);
    split_bf16(v.z,h2,l2); split_bf16(v.w,h3,l3);
    uint2 hw = make_uint2(pack_bf2(h0,h1), pack_bf2(h2,h3));
    uint2 lw = make_uint2(pack_bf2(l0,l1), pack_bf2(l2,l3));
    reinterpret_cast<uint2*>(H)[i] = hw;
    reinterpret_cast<uint2*>(L)[i] = lw;
}

// transpose + split: src [K][N] fp32 -> dst[n][k] bf16 hi/lo
__global__ void tconv_kernel(__nv_bfloat16* __restrict__ H, __nv_bfloat16* __restrict__ L,
                             const float* __restrict__ src, int K, int N) {
    __shared__ float t[32][33];
    int n0 = blockIdx.x * 32, k0 = blockIdx.y * 32;
    for (int yy = threadIdx.y; yy < 32; yy += 8)
        t[yy][threadIdx.x] = src[(long)(k0 + yy) * N + n0 + threadIdx.x];
    __syncthreads();
    for (int yy = threadIdx.y; yy < 32; yy += 8) {
        float v = t[threadIdx.x][yy];                  // src[k0+tx][n0+yy]
        long o = (long)(n0 + yy) * K + k0 + threadIdx.x;
        __nv_bfloat16 h, l; split_bf16(v, h, l);
        H[o] = h; L[o] = l;
    }
}

// memory K rows (fp32, later l2norm'd) + memory V columns (split, transposed) + vT pad zero
__global__ void memfill_kernel(float* __restrict__ kn,
                               __nv_bfloat16* __restrict__ vTH, __nv_bfloat16* __restrict__ vTL,
                               const float* __restrict__ mk, const float* __restrict__ mv) {
    int idx = blockIdx.x * blockDim.x + threadIdx.x;
    const int total = HH * NMEM * DHH;   // 16384
    if (idx >= total) return;
    int h   = idx / (NMEM * DHH);
    int rem = idx % (NMEM * DHH);
    int m = rem / DHH, d = rem % DHH;
    float k = mk[idx], v = mv[idx];
    __nv_bfloat16 vh, vl; split_bf16(v, vh, vl);
    for (int b = 0; b < Bc; b++) {
        kn[(((size_t)(b * HH + h) * JJ) + m) * DHH + d] = k;
        size_t base = ((size_t)(b * HH + h) * DHH + d) * JJP;
        vTH[base + m] = vh;            vTL[base + m] = vl;
        vTH[base + JJ + m] = __float2bfloat16(0.f);   // zero pad cols [2064,2080)
        vTL[base + JJ + m] = __float2bfloat16(0.f);
    }
}

// l2-normalize rows of 64 fp32 and emit split bf16; one warp per row
__global__ void l2norm_split_kernel(const float* __restrict__ src,
                                    __nv_bfloat16* __restrict__ H,
                                    __nv_bfloat16* __restrict__ L, int rows) {
    int row = blockIdx.x * 8 + (threadIdx.x >> 5);
    if (row >= rows) return;
    int lane = threadIdx.x & 31;
    float2 v = reinterpret_cast<const float2*>(src + (size_t)row * DHH)[lane];
    float ss = v.x * v.x + v.y * v.y;
    #pragma unroll
    for (int o = 16; o; o >>= 1) ss += __shfl_xor_sync(0xffffffffu, ss, o);
    float inv = 1.0f / fmaxf(sqrtf(ss), 1e-12f);
    __nv_bfloat16 hx,lx,hy,ly;
    split_bf16(v.x * inv, hx, lx);
    split_bf16(v.y * inv, hy, ly);
    reinterpret_cast<uint32_t*>(H)[(size_t)row * 32 + lane] = pack_bf2(hx, hy);
    reinterpret_cast<uint32_t*>(L)[(size_t)row * 32 + lane] = pack_bf2(lx, ly);
}

// ---------------- fused talking-heads pre-mix + softmax + post-mix ----------
// reads dots fp32 (pitch JJ), writes attn split bf16 (pitch JJP, pads zeroed)
__global__ void mix_softmax_kernel(const float* __restrict__ dots,
                                   __nv_bfloat16* __restrict__ atH,
                                   __nv_bfloat16* __restrict__ atL,
                                   const float* __restrict__ th_pre,
                                   const float* __restrict__ th_post) {
    extern __shared__ float sh[];                 // [16][JJ]
    __shared__ float s_pre[HH * HH], s_post[HH * HH];
    __shared__ float red[HH][8];
    __shared__ float gmax[HH], gsum[HH], Mmat[HH * HH];

    const int bi = blockIdx.x;
    const int b = bi / Nq, i = bi % Nq;
    const int tid = threadIdx.x;                  // 256
    const int warp = tid >> 5, lane = tid & 31;

    s_pre[tid]  = th_pre[tid];
    s_post[tid] = th_post[tid];

    for (int h = 0; h < HH; h++) {
        const float* src = dots + (((size_t)(b * HH + h) * Nq + i) * JJ);
        for (int j = tid; j < JJ; j += 256) sh[h * JJ + j] = src[j];
    }
    __syncthreads();

    float lmax[HH];
    #pragma unroll
    for (int g = 0; g < HH; g++) lmax[g] = -1e30f;
    for (int j = tid; j < JJ; j += 256) {
        float d[HH];
        #pragma unroll
        for (int h = 0; h < HH; h++) d[h] = sh[h * JJ + j];
        #pragma unroll
        for (int g = 0; g < HH; g++) {
            float m = 0.0f;
            #pragma unroll
            for (int h = 0; h < HH; h++) m = fmaf(s_pre[g * HH + h], d[h], m);
            sh[g * JJ + j] = m;
            lmax[g] = fmaxf(lmax[g], m);
        }
    }
    __syncthreads();
    #pragma unroll
    for (int g = 0; g < HH; g++) {
        float v = lmax[g];
        #pragma unroll
        for (int o = 16; o; o >>= 1) v = fmaxf(v, __shfl_xor_sync(0xffffffffu, v, o));
        if (lane == 0) red[g][warp] = v;
    }
    __syncthreads();
    if (tid < HH) {
        float v = red[tid][0];
        #pragma unroll
        for (int w = 1; w < 8; w++) v = fmaxf(v, red[tid][w]);
        gmax[tid] = v;
    }
    __syncthreads();

    float lsum[HH];
    #pragma unroll
    for (int g = 0; g < HH; g++) lsum[g] = 0.0f;
    for (int j = tid; j < JJ; j += 256) {
        #pragma unroll
        for (int g = 0; g < HH; g++) {
            float e = __expf(sh[g * JJ + j] - gmax[g]);
            sh[g * JJ + j] = e;
            lsum[g] += e;
        }
    }
    __syncthreads();
    #pragma unroll
    for (int g = 0; g < HH; g++) {
        float v = lsum[g];
        #pragma unroll
        for (int o = 16; o; o >>= 1) v += __shfl_xor_sync(0xffffffffu, v, o);
        if (lane == 0) red[g][warp] = v;
    }
    __syncthreads();
    if (tid < HH) {
        float v = 0.0f;
        #pragma unroll
        for (int w = 0; w < 8; w++) v += red[tid][w];
        gsum[tid] = v;
    }
    __syncthreads();
    Mmat[tid] = s_post[tid] / gsum[tid & 15];
    __syncthreads();

    for (int j = tid; j < JJP; j += 256) {
        float e[HH];
        bool in = (j < JJ);
        #pragma unroll
        for (int h = 0; h < HH; h++) e[h] = in ? sh[h * JJ + j] : 0.0f;
        #pragma unroll
        for (int g = 0; g < HH; g++) {
            float o = 0.0f;
            #pragma unroll
            for (int h = 0; h < HH; h++) o = fmaf(Mmat[g * HH + h], e[h], o);
            size_t oi = (((size_t)(b * HH + g) * Nq + i) * JJP) + j;
            __nv_bfloat16 oh, ol; split_bf16(o, oh, ol);
            atH[oi] = oh; atL[oi] = ol;
        }
    }
}

// ---------------- pre-split bf16x2 GEMM with cp.async pipeline --------------
// A: [M][K] bf16 hi/lo row-major.  B: [Nc][K] bf16 hi/lo row-major (n-major).
// C = A @ B^T, fp32 accum via 3-term mma (loH + hiL + hiH). K % 32 == 0.

__device__ __forceinline__ void cp16(uint32_t dst, const void* src) {
    asm volatile("cp.async.ca.shared.global [%0], [%1], 16;" :: "r"(dst), "l"(src));
}
__device__ __forceinline__ void cpcommit() { asm volatile("cp.async.commit_group;"); }
template<int N> __device__ __forceinline__ void cpwait() {
    asm volatile("cp.async.wait_group %0;" :: "n"(N));
}

__device__ __forceinline__ void mma_bf16(float* c, const uint32_t* a, const uint32_t* b) {
    asm volatile(
        "mma.sync.aligned.m16n8k16.row.col.f32.bf16.bf16.f32 "
        "{%0,%1,%2,%3}, {%4,%5,%6,%7}, {%8,%9}, {%0,%1,%2,%3};"
        : "+f"(c[0]), "+f"(c[1]), "+f"(c[2]), "+f"(c[3])
        : "r"(a[0]), "r"(a[1]), "r"(a[2]), "r"(a[3]),
          "r"(b[0]), "r"(b[1]));
}

template<int BM, int BN, int WM, int WN, bool GUARDN>
__global__ void __launch_bounds__((BM / WM) * (BN / WN) * 32)
psgemm_kernel(
    int M, int Nc, int K,
    const __nv_bfloat16* __restrict__ AH, const __nv_bfloat16* __restrict__ AL,
    long lda, long sA,
    const __nv_bfloat16* __restrict__ BH, const __nv_bfloat16* __restrict__ BL,
    long ldb, long sB,
    void* C0, void* C1, long sC,
    const float* __restrict__ alphaVec,
    float beta, int mode, int p1, int p2, int p3)
{
    constexpr int BK  = 32;
    constexpr int NTH = (BM / WM) * (BN / WN) * 32;
    constexpr int PA  = BK / 2 + 4;          // 20 u32 words (80B, 16B-aligned)
    constexpr int AW  = BM * PA;             // words per A array
    constexpr int BW  = BN * PA;             // words per B array
    constexpr int SW  = 2 * AW + 2 * BW;     // words per stage
    constexpr int MFR = WM / 16;
    constexpr int NFR = WN / 8;

    extern __shared__ uint32_t smem[];
    const uint32_t smem_addr = (uint32_t)__cvta_generic_to_shared(smem);

    const int z = blockIdx.z;
    const __nv_bfloat16* Ah = AH + (long)z * sA;
    const __nv_bfloat16* Al = AL + (long)z * sA;
    const __nv_bfloat16* Bh = BH + (long)z * sB;
    const __nv_bfloat16* Bl = BL + (long)z * sB;

    const int tid  = threadIdx.x;
    const int warp = tid >> 5;
    const int lane = tid & 31;
    const int g    = lane >> 2;
    const int tg   = lane & 3;
    const int wr   = warp / (BN / WN);
    const int wc   = warp % (BN / WN);
    const int rowBase = blockIdx.y * BM;
    const int colBase = blockIdx.x * BN;

    float acc[MFR][NFR][4];
    #pragma unroll
    for (int i = 0; i < MFR; i++)
        #pragma unroll
        for (int j = 0; j < NFR; j++)
            #pragma unroll
            for (int q = 0; q < 4; q++) acc[i][j][q] = 0.0f;

    auto load_tile = [&](int stage, int k0) {
        uint32_t base = smem_addr + (uint32_t)stage * SW * 4;
        // A: BM rows x 4 chunks of 8 bf16
        #pragma unroll 2
        for (int idx = tid; idx < BM * 4; idx += NTH) {
            int r  = idx >> 2;
            int c8 = idx & 3;
            long go = (long)(rowBase + r) * lda + k0 + c8 * 8;
            uint32_t d = base + (uint32_t)(r * PA + c8 * 4) * 4;
            cp16(d, Ah + go);
            cp16(d + AW * 4, Al + go);
        }
        // B: BN rows x 4 chunks
        #pragma unroll 2
        for (int idx = tid; idx < BN * 4; idx += NTH) {
            int c  = idx >> 2;
            int k8 = idx & 3;
            int gc = colBase + c;
            uint32_t d = base + (uint32_t)(2 * AW + c * PA + k8 * 4) * 4;
            if (!GUARDN || gc < Nc) {
                long go = (long)gc * ldb + k0 + k8 * 8;
                cp16(d, Bh + go);
                cp16(d + BW * 4, Bl + go);
            } else {
                uint4 zz = make_uint4(0, 0, 0, 0);
                *reinterpret_cast<uint4*>(&smem[stage * SW + 2 * AW + c * PA + k8 * 4]) = zz;
                *reinterpret_cast<uint4*>(&smem[stage * SW + 2 * AW + BW + c * PA + k8 * 4]) = zz;
            }
        }
    };

    const int nK = K / BK;
    load_tile(0, 0);
    cpcommit();

    for (int kt = 0; kt < nK; kt++) {
        int cur = kt & 1;
        if (kt + 1 < nK) load_tile((kt + 1) & 1, (kt + 1) * BK);
        cpcommit();
        cpwait<1>();
        __syncthreads();

        const uint32_t* AsH = smem + cur * SW;
        const uint32_t* AsL = AsH + AW;
        const uint32_t* BsH = AsH + 2 * AW;
        const uint32_t* BsL = BsH + BW;

        #pragma unroll
        for (int kk = 0; kk < BK; kk += 16) {
            const int kp = kk / 2;
            uint32_t afH[MFR][4], afL[MFR][4];
            uint32_t bfH[NFR][2], bfL[NFR][2];
            #pragma unroll
            for (int mi = 0; mi < MFR; mi++) {
                int mrow = wr * WM + mi * 16 + g;
                int i00 = (mrow    ) * PA + kp + tg;
                int i10 = (mrow + 8) * PA + kp + tg;
                afH[mi][0] = AsH[i00];     afL[mi][0] = AsL[i00];
                afH[mi][1] = AsH[i10];     afL[mi][1] = AsL[i10];
                afH[mi][2] = AsH[i00 + 4]; afL[mi][2] = AsL[i00 + 4];
                afH[mi][3] = AsH[i10 + 4]; afL[mi][3] = AsL[i10 + 4];
            }
            #pragma unroll
            for (int ni = 0; ni < NFR; ni++) {
                int ncol = wc * WN + ni * 8 + g;
                int j0 = ncol * PA + kp + tg;
                bfH[ni][0] = BsH[j0];     bfL[ni][0] = BsL[j0];
                bfH[ni][1] = BsH[j0 + 4]; bfL[ni][1] = BsL[j0 + 4];
            }
            #pragma unroll
            for (int mi = 0; mi < MFR; mi++)
                #pragma unroll
                for (int ni = 0; ni < NFR; ni++) {
                    float* c = acc[mi][ni];
                    mma_bf16(c, afL[mi], bfH[ni]);
                    mma_bf16(c, afH[mi], bfL[ni]);
                    mma_bf16(c, afH[mi], bfH[ni]);
                }
        }
        __syncthreads();
    }

    float alpha = 1.0f;
    if (alphaVec) alpha = alphaVec[z % HH];

    #pragma unroll
    for (int mi = 0; mi < MFR; mi++) {
        #pragma unroll
        for (int half = 0; half < 2; half++) {
            int gr = rowBase + wr * WM + mi * 16 + g + half * 8;
            if (gr >= M) continue;
            #pragma unroll
            for (int ni = 0; ni < NFR; ni++) {
                #pragma unroll
                for (int e = 0; e < 2; e++) {
                    int gc = colBase + wc * WN + ni * 8 + tg * 2 + e;
                    if (gc >= Nc) continue;
                    float val = alpha * acc[mi][ni][half * 2 + e];
                    if (mode == 0) {                      // plain fp32 + beta
                        float* cp = (float*)C0 + (long)gr * p1 + gc;
                        *cp = (beta == 0.0f) ? val : fmaf(beta, *cp, val);
                    } else if (mode == 1) {               // split-heads fp32 (q/k)
                        int b = gr / p1;
                        int rr = gr - b * p1;
                        int h = gc >> 6, d = gc & 63;
                        ((float*)C0)[(((long)(b * HH + h) * p2 + p3 + rr) << 6) + d] = val;
                    } else if (mode == 2) {               // cat split bf16
                        int b = z >> 4, h = z & 15;
                        long oi = (((long)(b * p1 + gr) * HH + h) << 6) + gc;
                        __nv_bfloat16 vh, vl; split_bf16(val, vh, vl);
                        ((__nv_bfloat16*)C0)[oi] = vh;
                        ((__nv_bfloat16*)C1)[oi] = vl;
                    } else if (mode == 3) {               // batched plain fp32
                        ((float*)C0)[(long)z * sC + (long)gr * p1 + gc] = val;
                    } else {                              // mode 4: vT split bf16
                        int b = gr / p1;
                        int rr = gr - b * p1;
                        int h = gc >> 6, d = gc & 63;
                        long oi = ((long)(b * HH + h) * DHH + d) * JJP + NMEM + rr;
                        __nv_bfloat16 vh, vl; split_bf16(val, vh, vl);
                        ((__nv_bfloat16*)C0)[oi] = vh;
                        ((__nv_bfloat16*)C1)[oi] = vl;
                    }
                }
            }
        }
    }
}

// ---------------- host launch ------------------------------------------------

static constexpr size_t MIX_SMEM  = (size_t)HH * JJ * sizeof(float);   // 132096
static constexpr int    BIG_SMEM  = 2 * (2 * 128 * 20 + 2 * 128 * 20) * 4;  // 81920
static constexpr int    SML_SMEM  = 2 * (2 * 64 * 20 + 2 * 64 * 20) * 4;    // 40960

extern "C" void kernel_launch(void* const* d_in, const int* in_sizes, int n_in,
                              void* d_out, int out_size)
{
    (void)in_sizes; (void)n_in; (void)out_size;
    const float* x   = (const float*)d_in[0];
    const float* ctx = (const float*)d_in[1];
    const float* wq[2]     = {(const float*)d_in[2],  (const float*)d_in[5]};
    const float* wk[2]     = {(const float*)d_in[3],  (const float*)d_in[6]};
    const float* wv[2]     = {(const float*)d_in[4],  (const float*)d_in[7]};
    const float* thpre[2]  = {(const float*)d_in[8],  (const float*)d_in[10]};
    const float* thpost[2] = {(const float*)d_in[9],  (const float*)d_in[11]};
    const float* scp[2]    = {(const float*)d_in[12], (const float*)d_in[13]};
    const float* mk[2]     = {(const float*)d_in[14], (const float*)d_in[16]};
    const float* mv[2]     = {(const float*)d_in[15], (const float*)d_in[17]};
    const float* hs[2]     = {(const float*)d_in[18], (const float*)d_in[19]};
    const float* wo[2]     = {(const float*)d_in[20], (const float*)d_in[21]};
    float* out = (float*)d_out;

    float *qn, *kn, *dots, *scl;
    __nv_bfloat16 *xH,*xL,*cH,*cL,*wTH,*wTL,*qnH,*qnL,*knH,*knL,*vTH,*vTL,*atH,*atL,*ctH,*ctL;
    cudaGetSymbolAddress((void**)&qn,   g_qn);
    cudaGetSymbolAddress((void**)&kn,   g_kn);
    cudaGetSymbolAddress((void**)&dots, g_dots);
    cudaGetSymbolAddress((void**)&scl,  g_scale);
    cudaGetSymbolAddress((void**)&xH,  g_xH);  cudaGetSymbolAddress((void**)&xL,  g_xL);
    cudaGetSymbolAddress((void**)&cH,  g_cH);  cudaGetSymbolAddress((void**)&cL,  g_cL);
    cudaGetSymbolAddress((void**)&wTH, g_wTH); cudaGetSymbolAddress((void**)&wTL, g_wTL);
    cudaGetSymbolAddress((void**)&qnH, g_qnH); cudaGetSymbolAddress((void**)&qnL, g_qnL);
    cudaGetSymbolAddress((void**)&knH, g_knH); cudaGetSymbolAddress((void**)&knL, g_knL);
    cudaGetSymbolAddress((void**)&vTH, g_vTH); cudaGetSymbolAddress((void**)&vTL, g_vTL);
    cudaGetSymbolAddress((void**)&atH, g_atH); cudaGetSymbolAddress((void**)&atL, g_atL);
    cudaGetSymbolAddress((void**)&ctH, g_ctH); cudaGetSymbolAddress((void**)&ctL, g_ctL);

    auto projk = psgemm_kernel<128, 128, 64, 32, false>;
    auto dotsk = psgemm_kernel<128, 128, 64, 32, true>;
    auto avk   = psgemm_kernel<64, 64, 32, 32, false>;
    cudaFuncSetAttribute(projk, cudaFuncAttributeMaxDynamicSharedMemorySize, BIG_SMEM);
    cudaFuncSetAttribute(dotsk, cudaFuncAttributeMaxDynamicSharedMemorySize, BIG_SMEM);
    cudaFuncSetAttribute(avk,   cudaFuncAttributeMaxDynamicSharedMemorySize, SML_SMEM);
    cudaFuncSetAttribute(mix_softmax_kernel,
                         cudaFuncAttributeMaxDynamicSharedMemorySize, (int)MIX_SMEM);

    // split x once (shared by both layers)
    split_kernel<<<(Bc * Nq * DIM / 4 + 255) / 256, 256>>>(xH, xL, x, (long)Bc * Nq * DIM / 4);

    for (int l = 0; l < 2; l++) {
        scale_kernel<<<1, 16>>>(scl, scp[l]);

        // split context for this layer
        split_kernel<<<(Bc * NCTX * DIM / 4 + 255) / 256, 256>>>(
            cH, cL, ctx + (size_t)l * Bc * NCTX * DIM, (long)Bc * NCTX * DIM / 4);

        // Q = x @ wq -> qn fp32 [b,h,n,d]
        tconv_kernel<<<dim3(HDH / 32, DIM / 32), dim3(32, 8)>>>(wTH, wTL, wq[l], DIM, HDH);
        projk<<<dim3(8, 16, 1), 256, BIG_SMEM>>>(
            Bc * Nq, HDH, DIM, xH, xL, DIM, 0, wTH, wTL, DIM, 0,
            qn, nullptr, 0, nullptr, 0.0f, 1, Nq, Nq, 0);

        // K = ctx @ wk -> kn fp32 rows [NMEM..JJ)
        tconv_kernel<<<dim3(HDH / 32, DIM / 32), dim3(32, 8)>>>(wTH, wTL, wk[l], DIM, HDH);
        projk<<<dim3(8, 32, 1), 256, BIG_SMEM>>>(
            Bc * NCTX, HDH, DIM, cH, cL, DIM, 0, wTH, wTL, DIM, 0,
            kn, nullptr, 0, nullptr, 0.0f, 1, NCTX, JJ, NMEM);

        // V = ctx @ wv -> vT split bf16 [(b,h),d][JJP], rows [NMEM..JJ)
        tconv_kernel<<<dim3(HDH / 32, DIM / 32), dim3(32, 8)>>>(wTH, wTL, wv[l], DIM, HDH);
        projk<<<dim3(8, 32, 1), 256, BIG_SMEM>>>(
            Bc * NCTX, HDH, DIM, cH, cL, DIM, 0, wTH, wTL, DIM, 0,
            vTH, vTL, 0, nullptr, 0.0f, 4, NCTX, 0, 0);

        memfill_kernel<<<64, 256>>>(kn, vTH, vTL, mk[l], mv[l]);

        l2norm_split_kernel<<<(Bc * HH * Nq + 7) / 8, 256>>>(qn, qnH, qnL, Bc * HH * Nq);
        l2norm_split_kernel<<<(Bc * HH * JJ + 7) / 8, 256>>>(kn, knH, knL, Bc * HH * JJ);

        // dots = scale[h] * qn @ kn^T  (z = b*16+h), fp32 out
        dotsk<<<dim3(17, 8, 32), 256, BIG_SMEM>>>(
            Nq, JJ, DHH, qnH, qnL, DHH, (long)Nq * DHH,
            knH, knL, DHH, (long)JJ * DHH,
            dots, nullptr, (long)Nq * JJ, scl, 0.0f, 3, JJ, 0, 0);

        // talking-heads mix + softmax -> attn split bf16 (pitch JJP)
        mix_softmax_kernel<<<Bc * Nq, 256, MIX_SMEM>>>(dots, atH, atL, thpre[l], thpost[l]);

        // out_heads = hs[h] * attn @ v -> cat split bf16 [b,n,(h,d)]
        avk<<<dim3(1, 16, 32), 128, SML_SMEM>>>(
            Nq, DHH, JJP, atH, atL, JJP, (long)Nq * JJP,
            vTH, vTL, JJP, (long)DHH * JJP,
            ctH, ctL, 0, hs[l], 0.0f, 2, Nq, 0, 0);

        // out (+)= cat @ wo
        tconv_kernel<<<dim3(DIM / 32, HDH / 32), dim3(32, 8)>>>(wTH, wTL, wo[l], HDH, DIM);
        projk<<<dim3(8, 16, 1), 256, BIG_SMEM>>>(
            Bc * Nq, DIM, HDH, ctH, ctL, HDH, 0, wTH, wTL, HDH, 0,
            out, nullptr, 0, nullptr, (l == 0 ? 0.0f : 1.0f), 0, DIM, 0, 0);
    }
}